// round 15
// baseline (speedup 1.0000x reference)
#include <cuda_runtime.h>
#include <cstdint>

#define N_NODES 50000
#define N_EDGES 800000
#define N_TOT_EDGES (N_EDGES + N_NODES)   // self-loops appended

// ------------------------- scratch (device globals; no allocs allowed) ------
__device__ float g_hf [(size_t)N_NODES * 512];   // per-layer GEMM output h
__device__ float g_buf[(size_t)N_NODES * 512];   // layer activation ping-pong
__device__ __align__(16) float g_as [N_NODES * 4];
__device__ __align__(16) float g_ad [N_NODES * 4];
// CSR by destination (built once per launch; graph static within a call)
__device__ int   g_deg [N_NODES];
__device__ int   g_off [N_NODES + 1];
__device__ int   g_cur [N_NODES];
__device__ int   g_srcs[N_TOT_EDGES];            // src ids grouped by dst

// ------------------------- shared GEMM helpers ------------------------------
__device__ __forceinline__ void mma8(float* d, const unsigned* a, const unsigned* b) {
    asm volatile(
        "mma.sync.aligned.m16n8k8.row.col.f32.tf32.tf32.f32 "
        "{%0,%1,%2,%3}, {%4,%5,%6,%7}, {%8,%9}, {%0,%1,%2,%3};"
        : "+f"(d[0]), "+f"(d[1]), "+f"(d[2]), "+f"(d[3])
        : "r"(a[0]), "r"(a[1]), "r"(a[2]), "r"(a[3]), "r"(b[0]), "r"(b[1]));
}

__device__ __forceinline__ void split_u(float v, unsigned& hi, unsigned& lo) {
    unsigned h = __float_as_uint(v) & 0xFFFFE000u;
    hi = h;
    lo = __float_as_uint(v - __uint_as_float(h));
}

__device__ __forceinline__ void cp_async16(uint32_t saddr, const void* gptr, int src_bytes) {
    asm volatile("cp.async.cg.shared.global [%0], [%1], 16, %2;"
        :: "r"(saddr), "l"(gptr), "r"(src_bytes));
}

#define BKC 32
#define SLD 36

// =============================================================================
// R9-proven GEMM: 128x128 CTA, 8 warps of 64x32, 2-stage cp.async,
// tf32 mma m16n8k8 with 2-term split (hi*hi + lo*hi + hi*lo).
// (tcgen05 is NOT available: harness targets sm_103 without the 'a' variant.)
// =============================================================================
#define BM 128
#define BN 128
#define GEMM_SMEM_BYTES (4 * 128 * SLD * 4)   // 72KB

__global__ __launch_bounds__(256) void mma_gemm_nt(
    const float* __restrict__ A, const float* __restrict__ W,
    float* __restrict__ C, const float* __restrict__ bias,
    int M, int Nout, int K, int relu)
{
    extern __shared__ float sm[];
    float* Asm[2] = { sm,               sm + 128 * SLD };
    float* Bsm[2] = { sm + 2*128*SLD,   sm + 3*128*SLD };
    uint32_t smem_u32;
    asm("{ .reg .u64 t; cvta.to.shared.u64 t, %1; cvt.u32.u64 %0, t; }"
        : "=r"(smem_u32) : "l"(sm));

    const int tid  = threadIdx.x;
    const int lane = tid & 31;
    const int wid  = tid >> 5;
    const int g    = lane >> 2;
    const int t    = lane & 3;
    const int wm   = (wid & 1) * 64;
    const int wn   = (wid >> 1) * 32;
    const int mBase = blockIdx.y * BM;
    const int nBase = blockIdx.x * BN;

    const int lr = tid >> 3;
    const int lc = (tid & 7) * 4;

    float acc[4][4][4];
    #pragma unroll
    for (int mt = 0; mt < 4; mt++)
        #pragma unroll
        for (int nt = 0; nt < 4; nt++)
            #pragma unroll
            for (int i = 0; i < 4; i++) acc[mt][nt][i] = 0.0f;

    const int nk = K / BKC;

    auto issue_chunk = [&](int ck, int b) {
        const int k0 = ck * BKC;
        const uint32_t aOff = smem_u32 + (uint32_t)(b * 128 * SLD) * 4;
        const uint32_t bOff = smem_u32 + (uint32_t)((2 + b) * 128 * SLD) * 4;
        #pragma unroll
        for (int i = 0; i < 4; i++) {
            int rr = lr + i * 32;
            int arow = mBase + rr;
            int ok = arow < M;
            const float* ag = A + (size_t)(ok ? arow : 0) * K + k0 + lc;
            cp_async16(aOff + (uint32_t)(rr * SLD + lc) * 4, ag, ok ? 16 : 0);
            const float* bg = W + (size_t)(nBase + rr) * K + k0 + lc;
            cp_async16(bOff + (uint32_t)(rr * SLD + lc) * 4, bg, 16);
        }
        asm volatile("cp.async.commit_group;");
    };

    issue_chunk(0, 0);

    for (int ck = 0; ck < nk; ck++) {
        const int cur = ck & 1;
        if (ck + 1 < nk) {
            issue_chunk(ck + 1, cur ^ 1);
            asm volatile("cp.async.wait_group 1;");
        } else {
            asm volatile("cp.async.wait_group 0;");
        }
        __syncthreads();

        const float* Ac = Asm[cur];
        const float* Bc = Bsm[cur];
        #pragma unroll
        for (int kk = 0; kk < 4; kk++) {
            const int kb = kk * 8;
            unsigned ah[4][4], al[4][4], bh[4][2], bl[4][2];
            #pragma unroll
            for (int mt = 0; mt < 4; mt++) {
                const float* p = Ac + (wm + mt * 16 + g) * SLD + kb + t;
                split_u(p[0],           ah[mt][0], al[mt][0]);
                split_u(p[8 * SLD],     ah[mt][1], al[mt][1]);
                split_u(p[4],           ah[mt][2], al[mt][2]);
                split_u(p[8 * SLD + 4], ah[mt][3], al[mt][3]);
            }
            #pragma unroll
            for (int nt = 0; nt < 4; nt++) {
                const float* p = Bc + (wn + nt * 8 + g) * SLD + kb + t;
                split_u(p[0], bh[nt][0], bl[nt][0]);
                split_u(p[4], bh[nt][1], bl[nt][1]);
            }
            #pragma unroll
            for (int mt = 0; mt < 4; mt++)
                #pragma unroll
                for (int nt = 0; nt < 4; nt++) {
                    mma8(acc[mt][nt], ah[mt], bh[nt]);
                    mma8(acc[mt][nt], al[mt], bh[nt]);
                    mma8(acc[mt][nt], ah[mt], bl[nt]);
                }
        }
        __syncthreads();
    }

    #pragma unroll
    for (int mt = 0; mt < 4; mt++) {
        int row0 = mBase + wm + mt * 16 + g;
        #pragma unroll
        for (int nt = 0; nt < 4; nt++) {
            int col = nBase + wn + nt * 8 + 2 * t;
            float b0 = bias ? bias[col]     : 0.f;
            float b1 = bias ? bias[col + 1] : 0.f;
            if (row0 < M) {
                float v0 = acc[mt][nt][0] + b0;
                float v1 = acc[mt][nt][1] + b1;
                if (relu) { v0 = fmaxf(v0, 0.f); v1 = fmaxf(v1, 0.f); }
                C[(size_t)row0 * Nout + col]     = v0;
                C[(size_t)row0 * Nout + col + 1] = v1;
            }
            if (row0 + 8 < M) {
                float v2 = acc[mt][nt][2] + b0;
                float v3 = acc[mt][nt][3] + b1;
                if (relu) { v2 = fmaxf(v2, 0.f); v3 = fmaxf(v3, 0.f); }
                C[(size_t)(row0 + 8) * Nout + col]     = v2;
                C[(size_t)(row0 + 8) * Nout + col + 1] = v3;
            }
        }
    }
}

// =============================================================================
// CSR build (once per launch)
// =============================================================================
__global__ void csr_count(const int* __restrict__ ei, int* __restrict__ deg) {
    int e = blockIdx.x * blockDim.x + threadIdx.x;
    if (e >= N_TOT_EDGES) return;
    int d = (e < N_EDGES) ? ei[N_EDGES + e] : (e - N_EDGES);
    atomicAdd(&deg[d], 1);
}

__global__ __launch_bounds__(1024) void csr_scan(
    const int* __restrict__ deg, int* __restrict__ off, int* __restrict__ cur)
{
    __shared__ int part[1024];
    const int tid = threadIdx.x;
    const int chunk = (N_NODES + 1023) / 1024;
    const int b = tid * chunk;
    const int e = min(b + chunk, N_NODES);
    int s = 0;
    for (int i = b; i < e; i++) s += deg[i];
    part[tid] = s;
    __syncthreads();
    for (int o = 1; o < 1024; o <<= 1) {
        int v = (tid >= o) ? part[tid - o] : 0;
        __syncthreads();
        part[tid] += v;
        __syncthreads();
    }
    int run = tid ? part[tid - 1] : 0;
    for (int i = b; i < e; i++) {
        off[i] = run; cur[i] = run;
        run += deg[i];
    }
    if (tid == 1023) off[N_NODES] = run;
}

__global__ void csr_scatter(const int* __restrict__ ei,
    int* __restrict__ cur, int* __restrict__ srcs)
{
    int e = blockIdx.x * blockDim.x + threadIdx.x;
    if (e >= N_TOT_EDGES) return;
    int s, d;
    if (e < N_EDGES) { s = ei[e]; d = ei[N_EDGES + e]; } else { s = d = e - N_EDGES; }
    int pos = atomicAdd(&cur[d], 1);
    srcs[pos] = s;
}

// ------------------------- per-node attention logits ------------------------
__global__ void compute_alphas(const float* __restrict__ hf,
    const float* __restrict__ a_src, const float* __restrict__ a_dst,
    float* __restrict__ as_, float* __restrict__ ad_, int H)
{
    int n    = blockIdx.x;
    int head = threadIdx.y;
    int lane = threadIdx.x;
    const float* hp = hf + ((size_t)n * H + head) * 128;
    float s1 = 0.f, s2 = 0.f;
    #pragma unroll
    for (int c = lane; c < 128; c += 32) {
        float hv = hp[c];
        s1 += hv * a_src[head*128 + c];
        s2 += hv * a_dst[head*128 + c];
    }
    #pragma unroll
    for (int o = 16; o > 0; o >>= 1) {
        s1 += __shfl_down_sync(0xffffffffu, s1, o);
        s2 += __shfl_down_sync(0xffffffffu, s2, o);
    }
    if (lane == 0) { as_[n*H + head] = s1; ad_[n*H + head] = s2; }
}

// =============================================================================
// Fused GAT aggregate, lane-batched softmax: one warp per (dst node, head).
// Phase 1: lane j computes alpha of edge beg+j (parallel gather + one MUFU
// for 32 edges); z = butterfly reduction. (s, alpha) staged via 256B smem.
// Phase 2: per edge, 2 broadcast LDS + independent float4 LDG + 4 FMA —
// consecutive-edge loads independent -> deep MLP instead of a serial
// (gather -> exp -> accumulate) chain per edge.
// =============================================================================
__global__ __launch_bounds__(256) void gat_aggregate(
    const int* __restrict__ off, const int* __restrict__ srcs,
    const float* __restrict__ as_, const float* __restrict__ ad_,
    const float* __restrict__ hf, const float* __restrict__ bias,
    float* __restrict__ out, int H, int relu)
{
    __shared__ int   ss[8][32];
    __shared__ float sa[8][32];
    const int wslot = threadIdx.x >> 5;
    const int gw    = (blockIdx.x * blockDim.x + threadIdx.x) >> 5;
    const int lane  = threadIdx.x & 31;
    if (gw >= N_NODES * H) return;
    const int n = gw / H;
    const int h = gw - n * H;

    const float adn = ad_[n*H + h];
    const int beg = off[n];
    const int end = off[n + 1];

    float4 acc = make_float4(0.f, 0.f, 0.f, 0.f);
    float zsum = 0.f;

    for (int base = beg; base < end; base += 32) {
        const int cnt = min(32, end - base);           // >= 1 (self-loops)
        // phase 1: per-lane alpha for edges [base, base+cnt)
        const int sl = srcs[base + min(lane, cnt - 1)];
        float e = as_[sl*H + h] + adn;
        e = e > 0.f ? e : 0.2f * e;
        const float a = (lane < cnt) ? __expf(e) : 0.f;
        ss[wslot][lane] = sl;
        sa[wslot][lane] = a;
        __syncwarp();

        float t = a;
        #pragma unroll
        for (int o = 16; o > 0; o >>= 1)
            t += __shfl_xor_sync(0xffffffffu, t, o);
        zsum += t;

        // phase 2: weighted gather-accumulate (same order as reference walk)
        #pragma unroll 4
        for (int j = 0; j < cnt; j++) {
            const int   s  = ss[wslot][j];
            const float aj = sa[wslot][j];
            const float4 hx = *(const float4*)(hf + (((size_t)s*H + h) << 7) + lane*4);
            acc.x = fmaf(aj, hx.x, acc.x);
            acc.y = fmaf(aj, hx.y, acc.y);
            acc.z = fmaf(aj, hx.z, acc.z);
            acc.w = fmaf(aj, hx.w, acc.w);
        }
        __syncwarp();                                   // before staging reuse
    }

    const float inv = 1.0f / (zsum + 1e-16f);
    const int hc = h * 128 + lane * 4;
    float4 r;
    r.x = acc.x * inv + bias[hc + 0];
    r.y = acc.y * inv + bias[hc + 1];
    r.z = acc.z * inv + bias[hc + 2];
    r.w = acc.w * inv + bias[hc + 3];
    if (relu) {
        r.x = fmaxf(r.x, 0.f); r.y = fmaxf(r.y, 0.f);
        r.z = fmaxf(r.z, 0.f); r.w = fmaxf(r.w, 0.f);
    }
    *(float4*)(out + ((size_t)n * H + h) * 128 + lane * 4) = r;
}

// ------------------------- host orchestration -------------------------------
static void launch_gemm(const float* A, const float* W, float* C,
                        const float* bias, int M, int Nout, int K, int relu)
{
    dim3 grid(Nout / BN, (M + BM - 1) / BM);
    mma_gemm_nt<<<grid, 256, GEMM_SMEM_BYTES>>>(A, W, C, bias, M, Nout, K, relu);
}

extern "C" void kernel_launch(void* const* d_in, const int* in_sizes, int n_in,
                              void* d_out, int out_size)
{
    const float* x   = (const float*)d_in[0];
    const int*   ei  = (const int*)  d_in[1];
    const float* W0  = (const float*)d_in[2];
    const float* as0 = (const float*)d_in[3];
    const float* ad0 = (const float*)d_in[4];
    const float* b0  = (const float*)d_in[5];
    const float* W1  = (const float*)d_in[6];
    const float* as1 = (const float*)d_in[7];
    const float* ad1 = (const float*)d_in[8];
    const float* b1  = (const float*)d_in[9];
    const float* W2  = (const float*)d_in[10];
    const float* as2 = (const float*)d_in[11];
    const float* ad2 = (const float*)d_in[12];
    const float* b2  = (const float*)d_in[13];
    const float* Wv  = (const float*)d_in[14];
    const float* bv  = (const float*)d_in[15];
    const float* Wt  = (const float*)d_in[16];
    const float* bt  = (const float*)d_in[17];

    cudaFuncSetAttribute(mma_gemm_nt,
                         cudaFuncAttributeMaxDynamicSharedMemorySize,
                         GEMM_SMEM_BYTES);

    float *hf, *buf, *as_, *ad_;
    int *deg, *off, *cur, *srcs;
    cudaGetSymbolAddress((void**)&hf,   g_hf);
    cudaGetSymbolAddress((void**)&buf,  g_buf);
    cudaGetSymbolAddress((void**)&as_,  g_as);
    cudaGetSymbolAddress((void**)&ad_,  g_ad);
    cudaGetSymbolAddress((void**)&deg,  g_deg);
    cudaGetSymbolAddress((void**)&off,  g_off);
    cudaGetSymbolAddress((void**)&cur,  g_cur);
    cudaGetSymbolAddress((void**)&srcs, g_srcs);

    float* out = (float*)d_out;
    float* h2  = out;                               // [N,128]
    float* xv  = out + (size_t)N_NODES * 128;       // [N,128]
    float* xt  = out + (size_t)N_NODES * 256;       // [N,128]

    // ---- CSR build ----
    cudaMemsetAsync(deg, 0, N_NODES * sizeof(int));
    csr_count  <<<(N_TOT_EDGES + 255)/256, 256>>>(ei, deg);
    csr_scan   <<<1, 1024>>>(deg, off, cur);
    csr_scatter<<<(N_TOT_EDGES + 255)/256, 256>>>(ei, cur, srcs);

    // layer 0: 512 -> 4x128, relu
    launch_gemm(x, W0, hf, nullptr, N_NODES, 512, 512, 0);
    compute_alphas<<<N_NODES, dim3(32, 4)>>>(hf, as0, ad0, as_, ad_, 4);
    gat_aggregate<<<(N_NODES * 4 * 32 + 255)/256, 256>>>(off, srcs, as_, ad_, hf, b0, buf, 4, 1);

    // layer 1: 512 -> 4x128, relu
    launch_gemm(buf, W1, hf, nullptr, N_NODES, 512, 512, 0);
    compute_alphas<<<N_NODES, dim3(32, 4)>>>(hf, as1, ad1, as_, ad_, 4);
    gat_aggregate<<<(N_NODES * 4 * 32 + 255)/256, 256>>>(off, srcs, as_, ad_, hf, b1, buf, 4, 1);

    // layer 2: 512 -> 1x128, no relu, writes h into d_out
    launch_gemm(buf, W2, hf, nullptr, N_NODES, 128, 512, 0);
    compute_alphas<<<N_NODES, dim3(32, 1)>>>(hf, as2, ad2, as_, ad_, 1);
    gat_aggregate<<<(N_NODES * 1 * 32 + 255)/256, 256>>>(off, srcs, as_, ad_, hf, b2, h2, 1, 0);

    // output heads (K=128, bias+relu)
    launch_gemm(h2, Wv, xv, bv, N_NODES, 128, 128, 1);
    launch_gemm(h2, Wt, xt, bt, N_NODES, 128, 128, 1);
}

// round 16
// speedup vs baseline: 1.4448x; 1.4448x over previous
#include <cuda_runtime.h>
#include <cstdint>

#define N_NODES 50000
#define N_EDGES 800000
#define N_TOT_EDGES (N_EDGES + N_NODES)   // self-loops appended

// ------------------------- scratch (device globals; no allocs allowed) ------
__device__ float g_hf [(size_t)N_NODES * 512];   // per-layer GEMM output h
__device__ float g_buf[(size_t)N_NODES * 512];   // layer activation ping-pong
__device__ __align__(16) float g_as [N_NODES * 4];
__device__ __align__(16) float g_ad [N_NODES * 4];
// CSR by destination (built once per launch; graph static within a call)
__device__ int   g_deg [N_NODES];
__device__ int   g_off [N_NODES + 1];
__device__ int   g_cur [N_NODES];
__device__ int   g_srcs[N_TOT_EDGES];            // src ids grouped by dst

// ------------------------- shared GEMM helpers ------------------------------
__device__ __forceinline__ void mma8(float* d, const unsigned* a, const unsigned* b) {
    asm volatile(
        "mma.sync.aligned.m16n8k8.row.col.f32.tf32.tf32.f32 "
        "{%0,%1,%2,%3}, {%4,%5,%6,%7}, {%8,%9}, {%0,%1,%2,%3};"
        : "+f"(d[0]), "+f"(d[1]), "+f"(d[2]), "+f"(d[3])
        : "r"(a[0]), "r"(a[1]), "r"(a[2]), "r"(a[3]), "r"(b[0]), "r"(b[1]));
}

__device__ __forceinline__ void split_u(float v, unsigned& hi, unsigned& lo) {
    unsigned h = __float_as_uint(v) & 0xFFFFE000u;
    hi = h;
    lo = __float_as_uint(v - __uint_as_float(h));
}

__device__ __forceinline__ void cp_async16(uint32_t saddr, const void* gptr, int src_bytes) {
    asm volatile("cp.async.cg.shared.global [%0], [%1], 16, %2;"
        :: "r"(saddr), "l"(gptr), "r"(src_bytes));
}

#define BKC 32
#define SLD 36

// =============================================================================
// R9-proven GEMM: 128x128 CTA, 8 warps of 64x32, 2-stage cp.async,
// tf32 mma m16n8k8 with 2-term split (hi*hi + lo*hi + hi*lo).
// (tcgen05 is NOT available: harness targets sm_103 without the 'a' variant.)
// =============================================================================
#define BM 128
#define BN 128
#define GEMM_SMEM_BYTES (4 * 128 * SLD * 4)   // 72KB

__global__ __launch_bounds__(256) void mma_gemm_nt(
    const float* __restrict__ A, const float* __restrict__ W,
    float* __restrict__ C, const float* __restrict__ bias,
    int M, int Nout, int K, int relu)
{
    extern __shared__ float sm[];
    float* Asm[2] = { sm,               sm + 128 * SLD };
    float* Bsm[2] = { sm + 2*128*SLD,   sm + 3*128*SLD };
    uint32_t smem_u32;
    asm("{ .reg .u64 t; cvta.to.shared.u64 t, %1; cvt.u32.u64 %0, t; }"
        : "=r"(smem_u32) : "l"(sm));

    const int tid  = threadIdx.x;
    const int lane = tid & 31;
    const int wid  = tid >> 5;
    const int g    = lane >> 2;
    const int t    = lane & 3;
    const int wm   = (wid & 1) * 64;
    const int wn   = (wid >> 1) * 32;
    const int mBase = blockIdx.y * BM;
    const int nBase = blockIdx.x * BN;

    const int lr = tid >> 3;
    const int lc = (tid & 7) * 4;

    float acc[4][4][4];
    #pragma unroll
    for (int mt = 0; mt < 4; mt++)
        #pragma unroll
        for (int nt = 0; nt < 4; nt++)
            #pragma unroll
            for (int i = 0; i < 4; i++) acc[mt][nt][i] = 0.0f;

    const int nk = K / BKC;

    auto issue_chunk = [&](int ck, int b) {
        const int k0 = ck * BKC;
        const uint32_t aOff = smem_u32 + (uint32_t)(b * 128 * SLD) * 4;
        const uint32_t bOff = smem_u32 + (uint32_t)((2 + b) * 128 * SLD) * 4;
        #pragma unroll
        for (int i = 0; i < 4; i++) {
            int rr = lr + i * 32;
            int arow = mBase + rr;
            int ok = arow < M;
            const float* ag = A + (size_t)(ok ? arow : 0) * K + k0 + lc;
            cp_async16(aOff + (uint32_t)(rr * SLD + lc) * 4, ag, ok ? 16 : 0);
            const float* bg = W + (size_t)(nBase + rr) * K + k0 + lc;
            cp_async16(bOff + (uint32_t)(rr * SLD + lc) * 4, bg, 16);
        }
        asm volatile("cp.async.commit_group;");
    };

    issue_chunk(0, 0);

    for (int ck = 0; ck < nk; ck++) {
        const int cur = ck & 1;
        if (ck + 1 < nk) {
            issue_chunk(ck + 1, cur ^ 1);
            asm volatile("cp.async.wait_group 1;");
        } else {
            asm volatile("cp.async.wait_group 0;");
        }
        __syncthreads();

        const float* Ac = Asm[cur];
        const float* Bc = Bsm[cur];
        #pragma unroll
        for (int kk = 0; kk < 4; kk++) {
            const int kb = kk * 8;
            unsigned ah[4][4], al[4][4], bh[4][2], bl[4][2];
            #pragma unroll
            for (int mt = 0; mt < 4; mt++) {
                const float* p = Ac + (wm + mt * 16 + g) * SLD + kb + t;
                split_u(p[0],           ah[mt][0], al[mt][0]);
                split_u(p[8 * SLD],     ah[mt][1], al[mt][1]);
                split_u(p[4],           ah[mt][2], al[mt][2]);
                split_u(p[8 * SLD + 4], ah[mt][3], al[mt][3]);
            }
            #pragma unroll
            for (int nt = 0; nt < 4; nt++) {
                const float* p = Bc + (wn + nt * 8 + g) * SLD + kb + t;
                split_u(p[0], bh[nt][0], bl[nt][0]);
                split_u(p[4], bh[nt][1], bl[nt][1]);
            }
            #pragma unroll
            for (int mt = 0; mt < 4; mt++)
                #pragma unroll
                for (int nt = 0; nt < 4; nt++) {
                    mma8(acc[mt][nt], ah[mt], bh[nt]);
                    mma8(acc[mt][nt], al[mt], bh[nt]);
                    mma8(acc[mt][nt], ah[mt], bl[nt]);
                }
        }
        __syncthreads();
    }

    #pragma unroll
    for (int mt = 0; mt < 4; mt++) {
        int row0 = mBase + wm + mt * 16 + g;
        #pragma unroll
        for (int nt = 0; nt < 4; nt++) {
            int col = nBase + wn + nt * 8 + 2 * t;
            float b0 = bias ? bias[col]     : 0.f;
            float b1 = bias ? bias[col + 1] : 0.f;
            if (row0 < M) {
                float v0 = acc[mt][nt][0] + b0;
                float v1 = acc[mt][nt][1] + b1;
                if (relu) { v0 = fmaxf(v0, 0.f); v1 = fmaxf(v1, 0.f); }
                C[(size_t)row0 * Nout + col]     = v0;
                C[(size_t)row0 * Nout + col + 1] = v1;
            }
            if (row0 + 8 < M) {
                float v2 = acc[mt][nt][2] + b0;
                float v3 = acc[mt][nt][3] + b1;
                if (relu) { v2 = fmaxf(v2, 0.f); v3 = fmaxf(v3, 0.f); }
                C[(size_t)(row0 + 8) * Nout + col]     = v2;
                C[(size_t)(row0 + 8) * Nout + col + 1] = v3;
            }
        }
    }
}

// =============================================================================
// CSR build (once per launch)
// =============================================================================
__global__ void csr_count(const int* __restrict__ ei, int* __restrict__ deg) {
    int e = blockIdx.x * blockDim.x + threadIdx.x;
    if (e >= N_TOT_EDGES) return;
    int d = (e < N_EDGES) ? ei[N_EDGES + e] : (e - N_EDGES);
    atomicAdd(&deg[d], 1);
}

__global__ __launch_bounds__(1024) void csr_scan(
    const int* __restrict__ deg, int* __restrict__ off, int* __restrict__ cur)
{
    __shared__ int part[1024];
    const int tid = threadIdx.x;
    const int chunk = (N_NODES + 1023) / 1024;
    const int b = tid * chunk;
    const int e = min(b + chunk, N_NODES);
    int s = 0;
    for (int i = b; i < e; i++) s += deg[i];
    part[tid] = s;
    __syncthreads();
    for (int o = 1; o < 1024; o <<= 1) {
        int v = (tid >= o) ? part[tid - o] : 0;
        __syncthreads();
        part[tid] += v;
        __syncthreads();
    }
    int run = tid ? part[tid - 1] : 0;
    for (int i = b; i < e; i++) {
        off[i] = run; cur[i] = run;
        run += deg[i];
    }
    if (tid == 1023) off[N_NODES] = run;
}

__global__ void csr_scatter(const int* __restrict__ ei,
    int* __restrict__ cur, int* __restrict__ srcs)
{
    int e = blockIdx.x * blockDim.x + threadIdx.x;
    if (e >= N_TOT_EDGES) return;
    int s, d;
    if (e < N_EDGES) { s = ei[e]; d = ei[N_EDGES + e]; } else { s = d = e - N_EDGES; }
    int pos = atomicAdd(&cur[d], 1);
    srcs[pos] = s;
}

// ------------------------- per-node attention logits ------------------------
__global__ void compute_alphas(const float* __restrict__ hf,
    const float* __restrict__ a_src, const float* __restrict__ a_dst,
    float* __restrict__ as_, float* __restrict__ ad_, int H)
{
    int n    = blockIdx.x;
    int head = threadIdx.y;
    int lane = threadIdx.x;
    const float* hp = hf + ((size_t)n * H + head) * 128;
    float s1 = 0.f, s2 = 0.f;
    #pragma unroll
    for (int c = lane; c < 128; c += 32) {
        float hv = hp[c];
        s1 += hv * a_src[head*128 + c];
        s2 += hv * a_dst[head*128 + c];
    }
    #pragma unroll
    for (int o = 16; o > 0; o >>= 1) {
        s1 += __shfl_down_sync(0xffffffffu, s1, o);
        s2 += __shfl_down_sync(0xffffffffu, s2, o);
    }
    if (lane == 0) { as_[n*H + head] = s1; ad_[n*H + head] = s2; }
}

// =============================================================================
// Fused GAT aggregate (R9-proven): one warp per (dst node, head).
// Max-free softmax (ratio-identical; logits O(1)), register accumulation,
// single store with 1/(z+eps), bias, relu. No atomics, no memset.
// =============================================================================
__global__ __launch_bounds__(256) void gat_aggregate(
    const int* __restrict__ off, const int* __restrict__ srcs,
    const float* __restrict__ as_, const float* __restrict__ ad_,
    const float* __restrict__ hf, const float* __restrict__ bias,
    float* __restrict__ out, int H, int relu)
{
    const int gw   = (blockIdx.x * blockDim.x + threadIdx.x) >> 5;
    const int lane = threadIdx.x & 31;
    if (gw >= N_NODES * H) return;
    const int n = gw / H;
    const int h = gw - n * H;

    const float adn = ad_[n*H + h];
    const int beg = off[n];
    const int end = off[n + 1];

    float4 acc = make_float4(0.f, 0.f, 0.f, 0.f);
    float zsum = 0.f;
    for (int i = beg; i < end; i++) {
        const int s = srcs[i];                       // uniform across warp
        float e = as_[s*H + h] + adn;                // broadcast load
        e = e > 0.f ? e : 0.2f * e;
        const float a = __expf(e);
        zsum += a;
        const float4 hx = *(const float4*)(hf + (((size_t)s*H + h) << 7) + lane*4);
        acc.x = fmaf(a, hx.x, acc.x);
        acc.y = fmaf(a, hx.y, acc.y);
        acc.z = fmaf(a, hx.z, acc.z);
        acc.w = fmaf(a, hx.w, acc.w);
    }
    const float inv = 1.0f / (zsum + 1e-16f);
    const int hc = h * 128 + lane * 4;
    float4 r;
    r.x = acc.x * inv + bias[hc + 0];
    r.y = acc.y * inv + bias[hc + 1];
    r.z = acc.z * inv + bias[hc + 2];
    r.w = acc.w * inv + bias[hc + 3];
    if (relu) {
        r.x = fmaxf(r.x, 0.f); r.y = fmaxf(r.y, 0.f);
        r.z = fmaxf(r.z, 0.f); r.w = fmaxf(r.w, 0.f);
    }
    *(float4*)(out + ((size_t)n * H + h) * 128 + lane * 4) = r;
}

// ------------------------- host orchestration -------------------------------
static void launch_gemm(const float* A, const float* W, float* C,
                        const float* bias, int M, int Nout, int K, int relu)
{
    dim3 grid(Nout / BN, (M + BM - 1) / BM);
    mma_gemm_nt<<<grid, 256, GEMM_SMEM_BYTES>>>(A, W, C, bias, M, Nout, K, relu);
}

extern "C" void kernel_launch(void* const* d_in, const int* in_sizes, int n_in,
                              void* d_out, int out_size)
{
    const float* x   = (const float*)d_in[0];
    const int*   ei  = (const int*)  d_in[1];
    const float* W0  = (const float*)d_in[2];
    const float* as0 = (const float*)d_in[3];
    const float* ad0 = (const float*)d_in[4];
    const float* b0  = (const float*)d_in[5];
    const float* W1  = (const float*)d_in[6];
    const float* as1 = (const float*)d_in[7];
    const float* ad1 = (const float*)d_in[8];
    const float* b1  = (const float*)d_in[9];
    const float* W2  = (const float*)d_in[10];
    const float* as2 = (const float*)d_in[11];
    const float* ad2 = (const float*)d_in[12];
    const float* b2  = (const float*)d_in[13];
    const float* Wv  = (const float*)d_in[14];
    const float* bv  = (const float*)d_in[15];
    const float* Wt  = (const float*)d_in[16];
    const float* bt  = (const float*)d_in[17];

    cudaFuncSetAttribute(mma_gemm_nt,
                         cudaFuncAttributeMaxDynamicSharedMemorySize,
                         GEMM_SMEM_BYTES);

    float *hf, *buf, *as_, *ad_;
    int *deg, *off, *cur, *srcs;
    cudaGetSymbolAddress((void**)&hf,   g_hf);
    cudaGetSymbolAddress((void**)&buf,  g_buf);
    cudaGetSymbolAddress((void**)&as_,  g_as);
    cudaGetSymbolAddress((void**)&ad_,  g_ad);
    cudaGetSymbolAddress((void**)&deg,  g_deg);
    cudaGetSymbolAddress((void**)&off,  g_off);
    cudaGetSymbolAddress((void**)&cur,  g_cur);
    cudaGetSymbolAddress((void**)&srcs, g_srcs);

    float* out = (float*)d_out;
    float* h2  = out;                               // [N,128]
    float* xv  = out + (size_t)N_NODES * 128;       // [N,128]
    float* xt  = out + (size_t)N_NODES * 256;       // [N,128]

    // ---- CSR build ----
    cudaMemsetAsync(deg, 0, N_NODES * sizeof(int));
    csr_count  <<<(N_TOT_EDGES + 255)/256, 256>>>(ei, deg);
    csr_scan   <<<1, 1024>>>(deg, off, cur);
    csr_scatter<<<(N_TOT_EDGES + 255)/256, 256>>>(ei, cur, srcs);

    // layer 0: 512 -> 4x128, relu
    launch_gemm(x, W0, hf, nullptr, N_NODES, 512, 512, 0);
    compute_alphas<<<N_NODES, dim3(32, 4)>>>(hf, as0, ad0, as_, ad_, 4);
    gat_aggregate<<<(N_NODES * 4 * 32 + 255)/256, 256>>>(off, srcs, as_, ad_, hf, b0, buf, 4, 1);

    // layer 1: 512 -> 4x128, relu
    launch_gemm(buf, W1, hf, nullptr, N_NODES, 512, 512, 0);
    compute_alphas<<<N_NODES, dim3(32, 4)>>>(hf, as1, ad1, as_, ad_, 4);
    gat_aggregate<<<(N_NODES * 4 * 32 + 255)/256, 256>>>(off, srcs, as_, ad_, hf, b1, buf, 4, 1);

    // layer 2: 512 -> 1x128, no relu, writes h into d_out
    launch_gemm(buf, W2, hf, nullptr, N_NODES, 128, 512, 0);
    compute_alphas<<<N_NODES, dim3(32, 1)>>>(hf, as2, ad2, as_, ad_, 1);
    gat_aggregate<<<(N_NODES * 1 * 32 + 255)/256, 256>>>(off, srcs, as_, ad_, hf, b2, h2, 1, 0);

    // output heads (K=128, bias+relu)
    launch_gemm(h2, Wv, xv, bv, N_NODES, 128, 128, 1);
    launch_gemm(h2, Wt, xt, bt, N_NODES, 128, 128, 1);
}

// round 17
// speedup vs baseline: 1.5982x; 1.1062x over previous
#include <cuda_runtime.h>
#include <cuda_bf16.h>
#include <cstdint>
#include <cstring>

#define N_NODES 50000
#define N_EDGES 800000
#define N_TOT_EDGES (N_EDGES + N_NODES)   // self-loops appended

// ------------------------- scratch (device globals; no allocs allowed) ------
__device__ float g_hf [(size_t)N_NODES * 512];   // per-layer GEMM output h
__device__ float g_buf[(size_t)N_NODES * 512];   // layer activation ping-pong
__device__ __align__(16) float g_as [N_NODES * 4];
__device__ __align__(16) float g_ad [N_NODES * 4];
// CSR by destination (built once per launch; graph static within a call)
__device__ int   g_deg [N_NODES];
__device__ int   g_off [N_NODES + 1];
__device__ int   g_cur [N_NODES];
__device__ int   g_srcs[N_TOT_EDGES];            // src ids grouped by dst

// ------------------------- GEMM helpers -------------------------------------
__device__ __forceinline__ void mma16(float* d, const unsigned* a, const unsigned* b) {
    asm volatile(
        "mma.sync.aligned.m16n8k16.row.col.f32.bf16.bf16.f32 "
        "{%0,%1,%2,%3}, {%4,%5,%6,%7}, {%8,%9}, {%0,%1,%2,%3};"
        : "+f"(d[0]), "+f"(d[1]), "+f"(d[2]), "+f"(d[3])
        : "r"(a[0]), "r"(a[1]), "r"(a[2]), "r"(a[3]), "r"(b[0]), "r"(b[1]));
}

// bf16 2-term split of a float pair: hi = rn_bf16(v), lo = rn_bf16(v - hi).
// (v - float(hi)) is exact in fp32, so dropped error per product is
// ~3*2^-18 relative — 16x the validated tf32-split class (measured 1.44e-5).
__device__ __forceinline__ void cvt2(float2 v, unsigned& hi, unsigned& lo) {
    __nv_bfloat162 h2 = __floats2bfloat162_rn(v.x, v.y);
    unsigned hu; memcpy(&hu, &h2, 4);
    const float hx = __uint_as_float(hu << 16);           // exact bf16->f32
    const float hy = __uint_as_float(hu & 0xFFFF0000u);
    __nv_bfloat162 l2 = __floats2bfloat162_rn(v.x - hx, v.y - hy);
    unsigned lu; memcpy(&lu, &l2, 4);
    hi = hu; lo = lu;
}

__device__ __forceinline__ void cp_async16(uint32_t saddr, const void* gptr, int src_bytes) {
    asm volatile("cp.async.cg.shared.global [%0], [%1], 16, %2;"
        :: "r"(saddr), "l"(gptr), "r"(src_bytes));
}

#define BKC 32
#define SLD 40    // 8g+2t spans all 16 even banks per half-warp phase (LDS.64)

// =============================================================================
// bf16-split GEMM: C = A[M,K] * W[Nout,K]^T (+bias, relu)
// Structure identical to the R9/R16-proven kernel (128x128 CTA, 8 warps of
// 64x32, 2-stage cp.async, raw fp32 smem); only the fragment path changes:
// m16n8k16 bf16 mma (2x MACs/instr of tf32 k8), contiguous k-pairs -> float2
// LDS, split at fragment-load time. 3 mmas per k16 step: hi*hi+lo*hi+hi*lo.
// Requires K % 32 == 0, Nout % 128 == 0 (true at all call sites).
// =============================================================================
#define BM 128
#define BN 128
#define GEMM_SMEM_BYTES (4 * 128 * SLD * 4)   // 80KB (2 CTAs/SM: 160KB <= 228KB)

__global__ __launch_bounds__(256) void mma_gemm_nt(
    const float* __restrict__ A, const float* __restrict__ W,
    float* __restrict__ C, const float* __restrict__ bias,
    int M, int Nout, int K, int relu)
{
    extern __shared__ float sm[];
    float* Asm[2] = { sm,               sm + 128 * SLD };
    float* Bsm[2] = { sm + 2*128*SLD,   sm + 3*128*SLD };
    uint32_t smem_u32;
    asm("{ .reg .u64 t; cvta.to.shared.u64 t, %1; cvt.u32.u64 %0, t; }"
        : "=r"(smem_u32) : "l"(sm));

    const int tid  = threadIdx.x;
    const int lane = tid & 31;
    const int wid  = tid >> 5;
    const int g    = lane >> 2;
    const int t    = lane & 3;
    const int wm   = (wid & 1) * 64;
    const int wn   = (wid >> 1) * 32;
    const int mBase = blockIdx.y * BM;
    const int nBase = blockIdx.x * BN;

    const int lr = tid >> 3;
    const int lc = (tid & 7) * 4;

    float acc[4][4][4];
    #pragma unroll
    for (int mt = 0; mt < 4; mt++)
        #pragma unroll
        for (int nt = 0; nt < 4; nt++)
            #pragma unroll
            for (int i = 0; i < 4; i++) acc[mt][nt][i] = 0.0f;

    const int nk = K / BKC;

    auto issue_chunk = [&](int ck, int b) {
        const int k0 = ck * BKC;
        const uint32_t aOff = smem_u32 + (uint32_t)(b * 128 * SLD) * 4;
        const uint32_t bOff = smem_u32 + (uint32_t)((2 + b) * 128 * SLD) * 4;
        #pragma unroll
        for (int i = 0; i < 4; i++) {
            int rr = lr + i * 32;
            int arow = mBase + rr;
            int ok = arow < M;
            const float* ag = A + (size_t)(ok ? arow : 0) * K + k0 + lc;
            cp_async16(aOff + (uint32_t)(rr * SLD + lc) * 4, ag, ok ? 16 : 0);
            const float* bg = W + (size_t)(nBase + rr) * K + k0 + lc;
            cp_async16(bOff + (uint32_t)(rr * SLD + lc) * 4, bg, 16);
        }
        asm volatile("cp.async.commit_group;");
    };

    issue_chunk(0, 0);

    for (int ck = 0; ck < nk; ck++) {
        const int cur = ck & 1;
        if (ck + 1 < nk) {
            issue_chunk(ck + 1, cur ^ 1);
            asm volatile("cp.async.wait_group 1;");
        } else {
            asm volatile("cp.async.wait_group 0;");
        }
        __syncthreads();

        const float* Ac = Asm[cur];
        const float* Bc = Bsm[cur];
        #pragma unroll
        for (int ks = 0; ks < 2; ks++) {           // two k16 steps per 32-chunk
            const int kb = ks * 16;
            unsigned ah[4][4], al[4][4], bh[4][2], bl[4][2];
            #pragma unroll
            for (int mt = 0; mt < 4; mt++) {
                const float* p0 = Ac + (wm + mt * 16 + g)     * SLD + kb + 2 * t;
                const float* p1 = Ac + (wm + mt * 16 + 8 + g) * SLD + kb + 2 * t;
                cvt2(*(const float2*)(p0),     ah[mt][0], al[mt][0]);  // (g,   k=2t..)
                cvt2(*(const float2*)(p1),     ah[mt][1], al[mt][1]);  // (g+8, k=2t..)
                cvt2(*(const float2*)(p0 + 8), ah[mt][2], al[mt][2]);  // (g,   k=2t+8..)
                cvt2(*(const float2*)(p1 + 8), ah[mt][3], al[mt][3]);  // (g+8, k=2t+8..)
            }
            #pragma unroll
            for (int nt = 0; nt < 4; nt++) {
                const float* p = Bc + (wn + nt * 8 + g) * SLD + kb + 2 * t;
                cvt2(*(const float2*)(p),     bh[nt][0], bl[nt][0]);
                cvt2(*(const float2*)(p + 8), bh[nt][1], bl[nt][1]);
            }
            #pragma unroll
            for (int mt = 0; mt < 4; mt++)
                #pragma unroll
                for (int nt = 0; nt < 4; nt++) {
                    mma16(acc[mt][nt], ah[mt], bh[nt]);   // hi*hi
                    mma16(acc[mt][nt], al[mt], bh[nt]);   // lo*hi
                    mma16(acc[mt][nt], ah[mt], bl[nt]);   // hi*lo
                }
        }
        __syncthreads();
    }

    #pragma unroll
    for (int mt = 0; mt < 4; mt++) {
        int row0 = mBase + wm + mt * 16 + g;
        #pragma unroll
        for (int nt = 0; nt < 4; nt++) {
            int col = nBase + wn + nt * 8 + 2 * t;
            float b0 = bias ? bias[col]     : 0.f;
            float b1 = bias ? bias[col + 1] : 0.f;
            if (row0 < M) {
                float v0 = acc[mt][nt][0] + b0;
                float v1 = acc[mt][nt][1] + b1;
                if (relu) { v0 = fmaxf(v0, 0.f); v1 = fmaxf(v1, 0.f); }
                C[(size_t)row0 * Nout + col]     = v0;
                C[(size_t)row0 * Nout + col + 1] = v1;
            }
            if (row0 + 8 < M) {
                float v2 = acc[mt][nt][2] + b0;
                float v3 = acc[mt][nt][3] + b1;
                if (relu) { v2 = fmaxf(v2, 0.f); v3 = fmaxf(v3, 0.f); }
                C[(size_t)(row0 + 8) * Nout + col]     = v2;
                C[(size_t)(row0 + 8) * Nout + col + 1] = v3;
            }
        }
    }
}

// =============================================================================
// CSR build (once per launch)
// =============================================================================
__global__ void csr_count(const int* __restrict__ ei, int* __restrict__ deg) {
    int e = blockIdx.x * blockDim.x + threadIdx.x;
    if (e >= N_TOT_EDGES) return;
    int d = (e < N_EDGES) ? ei[N_EDGES + e] : (e - N_EDGES);
    atomicAdd(&deg[d], 1);
}

__global__ __launch_bounds__(1024) void csr_scan(
    const int* __restrict__ deg, int* __restrict__ off, int* __restrict__ cur)
{
    __shared__ int part[1024];
    const int tid = threadIdx.x;
    const int chunk = (N_NODES + 1023) / 1024;
    const int b = tid * chunk;
    const int e = min(b + chunk, N_NODES);
    int s = 0;
    for (int i = b; i < e; i++) s += deg[i];
    part[tid] = s;
    __syncthreads();
    for (int o = 1; o < 1024; o <<= 1) {
        int v = (tid >= o) ? part[tid - o] : 0;
        __syncthreads();
        part[tid] += v;
        __syncthreads();
    }
    int run = tid ? part[tid - 1] : 0;
    for (int i = b; i < e; i++) {
        off[i] = run; cur[i] = run;
        run += deg[i];
    }
    if (tid == 1023) off[N_NODES] = run;
}

__global__ void csr_scatter(const int* __restrict__ ei,
    int* __restrict__ cur, int* __restrict__ srcs)
{
    int e = blockIdx.x * blockDim.x + threadIdx.x;
    if (e >= N_TOT_EDGES) return;
    int s, d;
    if (e < N_EDGES) { s = ei[e]; d = ei[N_EDGES + e]; } else { s = d = e - N_EDGES; }
    int pos = atomicAdd(&cur[d], 1);
    srcs[pos] = s;
}

// ------------------------- per-node attention logits ------------------------
__global__ void compute_alphas(const float* __restrict__ hf,
    const float* __restrict__ a_src, const float* __restrict__ a_dst,
    float* __restrict__ as_, float* __restrict__ ad_, int H)
{
    int n    = blockIdx.x;
    int head = threadIdx.y;
    int lane = threadIdx.x;
    const float* hp = hf + ((size_t)n * H + head) * 128;
    float s1 = 0.f, s2 = 0.f;
    #pragma unroll
    for (int c = lane; c < 128; c += 32) {
        float hv = hp[c];
        s1 += hv * a_src[head*128 + c];
        s2 += hv * a_dst[head*128 + c];
    }
    #pragma unroll
    for (int o = 16; o > 0; o >>= 1) {
        s1 += __shfl_down_sync(0xffffffffu, s1, o);
        s2 += __shfl_down_sync(0xffffffffu, s2, o);
    }
    if (lane == 0) { as_[n*H + head] = s1; ad_[n*H + head] = s2; }
}

// =============================================================================
// Fused GAT aggregate (R9/R16-proven): one warp per (dst node, head).
// Max-free softmax (ratio-identical; logits O(1)), register accumulation,
// single store with 1/(z+eps), bias, relu. No atomics, no memset.
// =============================================================================
__global__ __launch_bounds__(256) void gat_aggregate(
    const int* __restrict__ off, const int* __restrict__ srcs,
    const float* __restrict__ as_, const float* __restrict__ ad_,
    const float* __restrict__ hf, const float* __restrict__ bias,
    float* __restrict__ out, int H, int relu)
{
    const int gw   = (blockIdx.x * blockDim.x + threadIdx.x) >> 5;
    const int lane = threadIdx.x & 31;
    if (gw >= N_NODES * H) return;
    const int n = gw / H;
    const int h = gw - n * H;

    const float adn = ad_[n*H + h];
    const int beg = off[n];
    const int end = off[n + 1];

    float4 acc = make_float4(0.f, 0.f, 0.f, 0.f);
    float zsum = 0.f;
    for (int i = beg; i < end; i++) {
        const int s = srcs[i];                       // uniform across warp
        float e = as_[s*H + h] + adn;                // broadcast load
        e = e > 0.f ? e : 0.2f * e;
        const float a = __expf(e);
        zsum += a;
        const float4 hx = *(const float4*)(hf + (((size_t)s*H + h) << 7) + lane*4);
        acc.x = fmaf(a, hx.x, acc.x);
        acc.y = fmaf(a, hx.y, acc.y);
        acc.z = fmaf(a, hx.z, acc.z);
        acc.w = fmaf(a, hx.w, acc.w);
    }
    const float inv = 1.0f / (zsum + 1e-16f);
    const int hc = h * 128 + lane * 4;
    float4 r;
    r.x = acc.x * inv + bias[hc + 0];
    r.y = acc.y * inv + bias[hc + 1];
    r.z = acc.z * inv + bias[hc + 2];
    r.w = acc.w * inv + bias[hc + 3];
    if (relu) {
        r.x = fmaxf(r.x, 0.f); r.y = fmaxf(r.y, 0.f);
        r.z = fmaxf(r.z, 0.f); r.w = fmaxf(r.w, 0.f);
    }
    *(float4*)(out + ((size_t)n * H + h) * 128 + lane * 4) = r;
}

// ------------------------- host orchestration -------------------------------
static void launch_gemm(const float* A, const float* W, float* C,
                        const float* bias, int M, int Nout, int K, int relu)
{
    dim3 grid(Nout / BN, (M + BM - 1) / BM);
    mma_gemm_nt<<<grid, 256, GEMM_SMEM_BYTES>>>(A, W, C, bias, M, Nout, K, relu);
}

extern "C" void kernel_launch(void* const* d_in, const int* in_sizes, int n_in,
                              void* d_out, int out_size)
{
    const float* x   = (const float*)d_in[0];
    const int*   ei  = (const int*)  d_in[1];
    const float* W0  = (const float*)d_in[2];
    const float* as0 = (const float*)d_in[3];
    const float* ad0 = (const float*)d_in[4];
    const float* b0  = (const float*)d_in[5];
    const float* W1  = (const float*)d_in[6];
    const float* as1 = (const float*)d_in[7];
    const float* ad1 = (const float*)d_in[8];
    const float* b1  = (const float*)d_in[9];
    const float* W2  = (const float*)d_in[10];
    const float* as2 = (const float*)d_in[11];
    const float* ad2 = (const float*)d_in[12];
    const float* b2  = (const float*)d_in[13];
    const float* Wv  = (const float*)d_in[14];
    const float* bv  = (const float*)d_in[15];
    const float* Wt  = (const float*)d_in[16];
    const float* bt  = (const float*)d_in[17];

    cudaFuncSetAttribute(mma_gemm_nt,
                         cudaFuncAttributeMaxDynamicSharedMemorySize,
                         GEMM_SMEM_BYTES);

    float *hf, *buf, *as_, *ad_;
    int *deg, *off, *cur, *srcs;
    cudaGetSymbolAddress((void**)&hf,   g_hf);
    cudaGetSymbolAddress((void**)&buf,  g_buf);
    cudaGetSymbolAddress((void**)&as_,  g_as);
    cudaGetSymbolAddress((void**)&ad_,  g_ad);
    cudaGetSymbolAddress((void**)&deg,  g_deg);
    cudaGetSymbolAddress((void**)&off,  g_off);
    cudaGetSymbolAddress((void**)&cur,  g_cur);
    cudaGetSymbolAddress((void**)&srcs, g_srcs);

    float* out = (float*)d_out;
    float* h2  = out;                               // [N,128]
    float* xv  = out + (size_t)N_NODES * 128;       // [N,128]
    float* xt  = out + (size_t)N_NODES * 256;       // [N,128]

    // ---- CSR build ----
    cudaMemsetAsync(deg, 0, N_NODES * sizeof(int));
    csr_count  <<<(N_TOT_EDGES + 255)/256, 256>>>(ei, deg);
    csr_scan   <<<1, 1024>>>(deg, off, cur);
    csr_scatter<<<(N_TOT_EDGES + 255)/256, 256>>>(ei, cur, srcs);

    // layer 0: 512 -> 4x128, relu
    launch_gemm(x, W0, hf, nullptr, N_NODES, 512, 512, 0);
    compute_alphas<<<N_NODES, dim3(32, 4)>>>(hf, as0, ad0, as_, ad_, 4);
    gat_aggregate<<<(N_NODES * 4 * 32 + 255)/256, 256>>>(off, srcs, as_, ad_, hf, b0, buf, 4, 1);

    // layer 1: 512 -> 4x128, relu
    launch_gemm(buf, W1, hf, nullptr, N_NODES, 512, 512, 0);
    compute_alphas<<<N_NODES, dim3(32, 4)>>>(hf, as1, ad1, as_, ad_, 4);
    gat_aggregate<<<(N_NODES * 4 * 32 + 255)/256, 256>>>(off, srcs, as_, ad_, hf, b1, buf, 4, 1);

    // layer 2: 512 -> 1x128, no relu, writes h into d_out
    launch_gemm(buf, W2, hf, nullptr, N_NODES, 128, 512, 0);
    compute_alphas<<<N_NODES, dim3(32, 1)>>>(hf, as2, ad2, as_, ad_, 1);
    gat_aggregate<<<(N_NODES * 1 * 32 + 255)/256, 256>>>(off, srcs, as_, ad_, hf, b2, h2, 1, 0);

    // output heads (K=128, bias+relu)
    launch_gemm(h2, Wv, xv, bv, N_NODES, 128, 128, 1);
    launch_gemm(h2, Wt, xt, bt, N_NODES, 128, 128, 1);
}